// round 4
// baseline (speedup 1.0000x reference)
#include <cuda_runtime.h>
#include <cstdint>

// OR-tree reduction over rows of a (ROWS, 1024) float32 0/1 matrix.
// Reference pairwise-sum >= 0.5 tree == any(x >= 0.5) over the row for 0/1 data.
//
// One thread per row. Rows are 4KB apart -> every lane's load hits a distinct
// 128B line -> 32 L1tex wavefronts per LDG.128 per warp. The kernel is bound
// by (fixed launch overhead) + (L1tex wavefront queue) + (one DRAM trip), so
// minimize loads per thread:
//   Probe: 2 independent LDG.128 (8 floats). Per-thread unresolved prob 2^-8;
//   per-warp ~12% -> those warps' rescue lanes (expected 1-2 per warp) issue
//   8 more independent LDG.128 (divergence-predicated: only unresolved lanes
//   issue, so extra wavefronts are negligible) -> residual prob 2^-32.
//   A final full-scan loop preserves correctness for adversarial inputs.

static constexpr int COLS = 1024;
static constexpr int F4_PER_ROW = COLS / 4; // 256

__device__ __forceinline__ bool any_ge_half(const float4 v) {
    return (v.x >= 0.5f) | (v.y >= 0.5f) | (v.z >= 0.5f) | (v.w >= 0.5f);
}

__global__ void __launch_bounds__(128) vec_or_tree_kernel(
    const float* __restrict__ x,
    float* __restrict__ out,
    int rows)
{
    const int r = blockIdx.x * blockDim.x + threadIdx.x;
    if (r >= rows) return;

    const float4* __restrict__ row =
        reinterpret_cast<const float4*>(x) + (size_t)r * F4_PER_ROW;

    // Probe: 2 independent 16 B loads (one DRAM round trip, MLP=2).
    const float4 a = row[0];
    const float4 b = row[1];
    bool fired = any_ge_half(a) | any_ge_half(b);

    if (!fired) {
        // ~1/256 of threads: 8 independent loads (32 floats), one more trip.
        float4 v0 = row[2], v1 = row[3], v2 = row[4], v3 = row[5];
        float4 v4 = row[6], v5 = row[7], v6 = row[8], v7 = row[9];
        fired = any_ge_half(v0) | any_ge_half(v1) | any_ge_half(v2) |
                any_ge_half(v3) | any_ge_half(v4) | any_ge_half(v5) |
                any_ge_half(v6) | any_ge_half(v7);

        if (!fired) {
            // ~2^-32 per thread: correctness fallback, batched 8-wide.
            #pragma unroll 1
            for (int base = 10; base < F4_PER_ROW; base += 8) {
                bool hit = false;
                #pragma unroll
                for (int j = 0; j < 8; ++j) {
                    const float4 v = row[base + j];
                    hit |= any_ge_half(v);
                }
                if (hit) { fired = true; break; }
            }
        }
    }

    out[r] = fired ? 1.0f : 0.0f;
}

extern "C" void kernel_launch(void* const* d_in, const int* in_sizes, int n_in,
                              void* d_out, int out_size)
{
    const float* x = (const float*)d_in[0];
    float* out = (float*)d_out;
    const int rows = in_sizes[0] / COLS;   // 65536

    const int threads = 128;
    const int blocks = (rows + threads - 1) / threads;  // 512
    vec_or_tree_kernel<<<blocks, threads>>>(x, out, rows);
}